// round 15
// baseline (speedup 1.0000x reference)
#include <cuda_runtime.h>
#include <cuda_fp16.h>
#include <cstdint>

// out[8192,4096] = x[8192,4096] @ tanh(blocks*mask); blocks = 16 diag blocks 256x256.
// Raw mma.sync.m16n8k16 fp16 (rel_err ~2.8e-4). R13 data path + NEW schedule:
// 3-stage smem pipeline, ONE __syncthreads per K-chunk, and >=1 full chunk of
// slack on every async op (cp.async B two chunks ahead, LDG A two chunks ahead,
// cvt one chunk ahead) to kill the barrier-convoy exposure seen in R8/R13.

#define LAYER 4096
#define NROWS 8192
#define NBLK  16
#define BSZ   256
#define KCH   64
#define LDA   72   // fp16 elems; 144 B row stride -> ldmatrix rows hit distinct banks
#define LDB   72

__device__ __align__(16) __half g_B[NBLK * BSZ * BSZ];  // [blk][n][k]

__device__ __forceinline__ uint32_t smem_u32(const void* p) {
    uint32_t a;
    asm("{ .reg .u64 t; cvta.to.shared.u64 t, %1; cvt.u32.u64 %0, t; }" : "=r"(a) : "l"(p));
    return a;
}
__device__ __forceinline__ uint32_t h2u(__half2 h) {
    return *reinterpret_cast<uint32_t*>(&h);
}

// ---------------- Stage 1: tanh + transpose blocks ----------------
__global__ __launch_bounds__(256) void prep_B(const float* __restrict__ blocks) {
    __shared__ float v[32][BSZ + 1];
    const int kt  = blockIdx.x;   // 0..7
    const int blk = blockIdx.y;   // 0..15
    const int tid = threadIdx.x;

    #pragma unroll
    for (int i = 0; i < 32; i++) {
        int idx = tid + i * 256;
        int k = idx >> 8, n = idx & 255;
        v[k][n] = blocks[(size_t)(blk * BSZ + kt * 32 + k) * LAYER + (size_t)(blk * BSZ + n)];
    }
    __syncthreads();

    const int n = tid;
    uint32_t w[16];
    #pragma unroll
    for (int k2 = 0; k2 < 16; k2++) {
        float t0 = tanhf(v[2 * k2][n]);
        float t1 = tanhf(v[2 * k2 + 1][n]);
        w[k2] = h2u(__floats2half2_rn(t0, t1));
    }
    size_t base = (size_t)(blk * BSZ + n) * BSZ + kt * 32;  // [blk][n][k]
    #pragma unroll
    for (int q = 0; q < 4; q++)
        *reinterpret_cast<uint4*>(&g_B[base + q * 8]) =
            make_uint4(w[4 * q], w[4 * q + 1], w[4 * q + 2], w[4 * q + 3]);
}

// ---------------- Stage 2: mma.sync GEMM, 3-stage pipeline ----------------
// per stage: sA 18432 B | sB 36864 B = 55296; 3 stages = 165888 B
#define STG_BYTES 55296
#define SB_OFF    18432
#define SM_TOTAL  (3 * STG_BYTES)

__device__ __forceinline__ void mma16816(float* d, const uint32_t* a, const uint32_t* b) {
    asm volatile(
        "mma.sync.aligned.m16n8k16.row.col.f32.f16.f16.f32 "
        "{%0,%1,%2,%3}, {%4,%5,%6,%7}, {%8,%9}, {%0,%1,%2,%3};"
        : "+f"(d[0]), "+f"(d[1]), "+f"(d[2]), "+f"(d[3])
        : "r"(a[0]), "r"(a[1]), "r"(a[2]), "r"(a[3]), "r"(b[0]), "r"(b[1]));
}
__device__ __forceinline__ void ldsm4(uint32_t* r, uint32_t addr) {
    asm volatile("ldmatrix.sync.aligned.m8n8.x4.shared.b16 {%0,%1,%2,%3}, [%4];"
                 : "=r"(r[0]), "=r"(r[1]), "=r"(r[2]), "=r"(r[3]) : "r"(addr));
}

__global__ void __launch_bounds__(512, 1) bd_mma(const float* __restrict__ x,
                                                 float* __restrict__ out) {
    extern __shared__ __align__(16) char smem[];
    const uint32_t sbase = smem_u32(smem);
    const int tid  = threadIdx.x;
    const int w    = tid >> 5;
    const int lane = tid & 31;
    const int wm   = w & 3;          // 0..3 -> 32-row band
    const int wn   = w >> 2;         // 0..3 -> 64-col band
    const int mTile = blockIdx.x;    // 0..63
    const int blk   = blockIdx.y;    // 0..15

    const float*  Asrc = x + (size_t)mTile * 128 * LAYER + (size_t)blk * BSZ;
    const __half* Bsrc = g_B + (size_t)blk * BSZ * BSZ;

    // ldmatrix lane-address components
    const int mi    = lane >> 3;
    const int lane7 = lane & 7;
    const int aRowL = (mi & 1) * 8 + lane7;
    const int aKoff = (mi >> 1) * 8;
    const int bNoff = (mi >> 1) * 8 + lane7;
    const int bKoff = (mi & 1) * 8;

    float d[2][8][4];
    #pragma unroll
    for (int mt = 0; mt < 2; mt++)
        #pragma unroll
        for (int o = 0; o < 8; o++)
            #pragma unroll
            for (int e = 0; e < 4; e++) d[mt][o][e] = 0.0f;

    float4 aReg[4];

    // helper lambdas (inlined by compiler)
    auto ldgA = [&](int c) {
        #pragma unroll
        for (int i = 0; i < 4; i++) {
            int f = tid + i * 512;
            int row = f >> 4, c4 = f & 15;
            aReg[i] = *reinterpret_cast<const float4*>(
                Asrc + (size_t)row * LAYER + c * KCH + c4 * 4);
        }
    };
    auto cvtA = [&](int stage) {
        __half* sAp = reinterpret_cast<__half*>(smem + stage * STG_BYTES);
        #pragma unroll
        for (int i = 0; i < 4; i++) {
            int f = tid + i * 512;
            int row = f >> 4, c4 = f & 15;
            __half2 h01 = __floats2half2_rn(aReg[i].x, aReg[i].y);
            __half2 h23 = __floats2half2_rn(aReg[i].z, aReg[i].w);
            *reinterpret_cast<uint2*>(sAp + row * LDA + c4 * 4) = make_uint2(h2u(h01), h2u(h23));
        }
    };
    auto cpB = [&](int c, int stage) {
        uint32_t dstB = sbase + stage * STG_BYTES + SB_OFF;
        #pragma unroll
        for (int i = 0; i < 4; i++) {
            int u = tid + i * 512;
            int n = u >> 3, q = u & 7;
            uint32_t dst = dstB + (uint32_t)(n * LDB + q * 8) * 2;
            const __half* src = Bsrc + (size_t)n * BSZ + c * KCH + q * 8;
            asm volatile("cp.async.ca.shared.global [%0], [%1], 16;" :: "r"(dst), "l"(src) : "memory");
        }
        asm volatile("cp.async.commit_group;" ::: "memory");
    };

    // ---- prologue ----
    ldgA(0);
    cpB(0, 0);           // group: B0
    cvtA(0);             // A0 -> sA[0]
    ldgA(1);             // A1 -> regs
    cpB(1, 1);           // group: B1
    asm volatile("cp.async.wait_group 1;" ::: "memory");   // B0 done
    __syncthreads();

    // ---- mainloop: one sync per chunk; everything prefetched >=1 chunk ahead ----
    #pragma unroll
    for (int c = 0; c < 4; c++) {
        const int stage = c % 3;
        const uint32_t sA = sbase + stage * STG_BYTES;
        const uint32_t sB = sA + SB_OFF;

        if (c + 1 < 4) cvtA((c + 1) % 3);    // aReg holds A(c+1); stage free since c-2
        if (c + 2 < 4) {
            ldgA(c + 2);                      // lands during this chunk's MMAs
            cpB(c + 2, (c + 2) % 3);          // waited at end of NEXT iteration
        }

        // ---- MMA over stage: 4 ksteps ----
        #pragma unroll
        for (int ks = 0; ks < 4; ks++) {
            uint32_t af[2][4];
            ldsm4(af[0], sA + (uint32_t)((wm * 32      + aRowL) * LDA + ks * 16 + aKoff) * 2);
            ldsm4(af[1], sA + (uint32_t)((wm * 32 + 16 + aRowL) * LDA + ks * 16 + aKoff) * 2);
            uint32_t bf[8][2];
            #pragma unroll
            for (int q = 0; q < 4; q++) {
                uint32_t r[4];
                ldsm4(r, sB + (uint32_t)((wn * 64 + q * 16 + bNoff) * LDB + ks * 16 + bKoff) * 2);
                bf[2 * q][0] = r[0]; bf[2 * q][1] = r[1];
                bf[2 * q + 1][0] = r[2]; bf[2 * q + 1][1] = r[3];
            }
            #pragma unroll
            for (int o = 0; o < 8; o++) {
                mma16816(d[0][o], af[0], bf[o]);
                mma16816(d[1][o], af[1], bf[o]);
            }
        }

        // ---- close chunk: B(c+1) must have landed; publish cvt writes ----
        if (c < 3) {
            if (c < 2) {
                asm volatile("cp.async.wait_group 1;" ::: "memory");  // all but newest
            } else {
                asm volatile("cp.async.wait_group 0;" ::: "memory");  // drain (B3)
            }
            __syncthreads();
        }
    }

    // ---- epilogue ----
    const int colBase = blk * BSZ + wn * 64 + (lane & 3) * 2;
    const int rowBase = mTile * 128 + wm * 32 + (lane >> 2);
    #pragma unroll
    for (int mt = 0; mt < 2; mt++) {
        float* r0 = out + (size_t)(rowBase + mt * 16) * LAYER + colBase;
        float* r1 = r0 + 8 * LAYER;
        #pragma unroll
        for (int o = 0; o < 8; o++) {
            *reinterpret_cast<float2*>(r0 + o * 8) = make_float2(d[mt][o][0], d[mt][o][1]);
            *reinterpret_cast<float2*>(r1 + o * 8) = make_float2(d[mt][o][2], d[mt][o][3]);
        }
    }
}

// ---------------- launch ----------------
extern "C" void kernel_launch(void* const* d_in, const int* in_sizes, int n_in,
                              void* d_out, int out_size) {
    const float* x      = (const float*)d_in[0];
    const float* blocks = (const float*)d_in[1];
    float* out = (float*)d_out;
    (void)in_sizes; (void)n_in; (void)out_size;

    cudaFuncSetAttribute(bd_mma, cudaFuncAttributeMaxDynamicSharedMemorySize, SM_TOTAL);

    prep_B<<<dim3(8, NBLK), 256>>>(blocks);
    bd_mma<<<dim3(NROWS / 128, NBLK), 512, SM_TOTAL>>>(x, out);
}

// round 16
// speedup vs baseline: 1.1191x; 1.1191x over previous
#include <cuda_runtime.h>
#include <cuda_fp16.h>
#include <cstdint>

// out[8192,4096] = x[8192,4096] @ tanh(blocks*mask); blocks = 16 diag blocks 256x256.
// Raw mma.sync.m16n8k16 fp16. NEW: 64x64 warp tiles (8 warps, 256 thr) over the
// 128x256 CTA tile -> per-warp kstep is 8 ldsm.x4 : 32 independent MMAs
// (was 6:16). CTA ldsm traffic drops 33% and each warp carries a 32-deep
// independent MMA burst, letting LSU and tensor overlap instead of serializing
// (R13 measured wall ~= L1busy + tensorbusy). Schedule = proven R8/R13:
// double-buffered smem, cp.async B, reg-prefetched A with in-reg fp32->fp16 cvt.

#define LAYER 4096
#define NROWS 8192
#define NBLK  16
#define BSZ   256
#define KCH   64
#define LDA   72   // fp16 elems; 144 B row stride -> ldmatrix rows on distinct banks
#define LDB   72

__device__ __align__(16) __half g_B[NBLK * BSZ * BSZ];  // [blk][n][k]

__device__ __forceinline__ uint32_t smem_u32(const void* p) {
    uint32_t a;
    asm("{ .reg .u64 t; cvta.to.shared.u64 t, %1; cvt.u32.u64 %0, t; }" : "=r"(a) : "l"(p));
    return a;
}
__device__ __forceinline__ uint32_t h2u(__half2 h) {
    return *reinterpret_cast<uint32_t*>(&h);
}

// ---------------- Stage 1: tanh + transpose blocks ----------------
__global__ __launch_bounds__(256) void prep_B(const float* __restrict__ blocks) {
    __shared__ float v[32][BSZ + 1];
    const int kt  = blockIdx.x;   // 0..7
    const int blk = blockIdx.y;   // 0..15
    const int tid = threadIdx.x;

    #pragma unroll
    for (int i = 0; i < 32; i++) {
        int idx = tid + i * 256;
        int k = idx >> 8, n = idx & 255;
        v[k][n] = blocks[(size_t)(blk * BSZ + kt * 32 + k) * LAYER + (size_t)(blk * BSZ + n)];
    }
    __syncthreads();

    const int n = tid;
    uint32_t w[16];
    #pragma unroll
    for (int k2 = 0; k2 < 16; k2++) {
        float t0 = tanhf(v[2 * k2][n]);
        float t1 = tanhf(v[2 * k2 + 1][n]);
        w[k2] = h2u(__floats2half2_rn(t0, t1));
    }
    size_t base = (size_t)(blk * BSZ + n) * BSZ + kt * 32;  // [blk][n][k]
    #pragma unroll
    for (int q = 0; q < 4; q++)
        *reinterpret_cast<uint4*>(&g_B[base + q * 8]) =
            make_uint4(w[4 * q], w[4 * q + 1], w[4 * q + 2], w[4 * q + 3]);
}

// ---------------- Stage 2: mma.sync GEMM, 64x64 warp tiles ----------------
// dyn smem: sA0 18432 | sA1 18432 | sB0 36864 | sB1 36864 = 110592 B
#define SMA0 0
#define SMA1 18432
#define SMB0 36864
#define SMB1 73728
#define SM_TOTAL 110592

__device__ __forceinline__ void mma16816(float* d, const uint32_t* a, const uint32_t* b) {
    asm volatile(
        "mma.sync.aligned.m16n8k16.row.col.f32.f16.f16.f32 "
        "{%0,%1,%2,%3}, {%4,%5,%6,%7}, {%8,%9}, {%0,%1,%2,%3};"
        : "+f"(d[0]), "+f"(d[1]), "+f"(d[2]), "+f"(d[3])
        : "r"(a[0]), "r"(a[1]), "r"(a[2]), "r"(a[3]), "r"(b[0]), "r"(b[1]));
}
__device__ __forceinline__ void ldsm4(uint32_t* r, uint32_t addr) {
    asm volatile("ldmatrix.sync.aligned.m8n8.x4.shared.b16 {%0,%1,%2,%3}, [%4];"
                 : "=r"(r[0]), "=r"(r[1]), "=r"(r[2]), "=r"(r[3]) : "r"(addr));
}

__global__ void __launch_bounds__(256, 1) bd_mma(const float* __restrict__ x,
                                                 float* __restrict__ out) {
    extern __shared__ __align__(16) char smem[];
    const uint32_t sbase = smem_u32(smem);
    const int tid  = threadIdx.x;
    const int w    = tid >> 5;
    const int lane = tid & 31;
    const int wm   = w >> 2;         // 0..1 -> 64-row band
    const int wn   = w & 3;          // 0..3 -> 64-col band
    const int mTile = blockIdx.x;    // 0..63
    const int blk   = blockIdx.y;    // 0..15

    const float*  Asrc = x + (size_t)mTile * 128 * LAYER + (size_t)blk * BSZ;
    const __half* Bsrc = g_B + (size_t)blk * BSZ * BSZ;

    // ldmatrix lane-address components
    const int mi    = lane >> 3;
    const int lane7 = lane & 7;
    const int aRowL = (mi & 1) * 8 + lane7;   // row within 16-row frag
    const int aKoff = (mi >> 1) * 8;          // k offset within kstep
    const int bNoff = (mi >> 1) * 8 + lane7;  // n within 16-n group (2 octets)
    const int bKoff = (mi & 1) * 8;

    // accumulators: 4 M-frags x 8 N-octets x 4 = 128 regs
    float d[4][8][4];
    #pragma unroll
    for (int mf = 0; mf < 4; mf++)
        #pragma unroll
        for (int o = 0; o < 8; o++)
            #pragma unroll
            for (int e = 0; e < 4; e++) d[mf][o][e] = 0.0f;

    float4 aReg[8];   // A chunk: 128 rows x 16 float4 = 2048 ids / 256 thr

    // ---- prologue: A(0) -> regs, B(0) -> sB0 via cp.async ----
    #pragma unroll
    for (int i = 0; i < 8; i++) {
        int f = tid + i * 256;
        int row = f >> 4, c4 = f & 15;
        aReg[i] = *reinterpret_cast<const float4*>(Asrc + (size_t)row * LAYER + c4 * 4);
    }
    #pragma unroll
    for (int i = 0; i < 8; i++) {                  // B: 256 n x 8 uint4 = 2048 ids
        int u = tid + i * 256;
        int n = u >> 3, q = u & 7;
        uint32_t dst = sbase + SMB0 + (uint32_t)(n * LDB + q * 8) * 2;
        const __half* src = Bsrc + (size_t)n * BSZ + q * 8;
        asm volatile("cp.async.ca.shared.global [%0], [%1], 16;" :: "r"(dst), "l"(src) : "memory");
    }
    asm volatile("cp.async.commit_group;" ::: "memory");

    for (int c = 0; c < 4; c++) {
        const int buf = c & 1;
        const uint32_t sA = sbase + (buf ? SMA1 : SMA0);
        const uint32_t sB = sbase + (buf ? SMB1 : SMB0);
        __half* sAp = reinterpret_cast<__half*>(smem + (buf ? SMA1 : SMA0));

        // ---- convert A regs -> sA (fp16) ----
        #pragma unroll
        for (int i = 0; i < 8; i++) {
            int f = tid + i * 256;
            int row = f >> 4, c4 = f & 15;
            __half2 h01 = __floats2half2_rn(aReg[i].x, aReg[i].y);
            __half2 h23 = __floats2half2_rn(aReg[i].z, aReg[i].w);
            *reinterpret_cast<uint2*>(sAp + row * LDA + c4 * 4) = make_uint2(h2u(h01), h2u(h23));
        }

        // ---- prefetch chunk c+1 (A -> regs, B -> other buffer) ----
        if (c < 3) {
            #pragma unroll
            for (int i = 0; i < 8; i++) {
                int f = tid + i * 256;
                int row = f >> 4, c4 = f & 15;
                aReg[i] = *reinterpret_cast<const float4*>(
                    Asrc + (size_t)row * LAYER + (c + 1) * KCH + c4 * 4);
            }
            uint32_t sbB = sbase + (((c + 1) & 1) ? SMB1 : SMB0);
            #pragma unroll
            for (int i = 0; i < 8; i++) {
                int u = tid + i * 256;
                int n = u >> 3, q = u & 7;
                uint32_t dst = sbB + (uint32_t)(n * LDB + q * 8) * 2;
                const __half* src = Bsrc + (size_t)n * BSZ + (c + 1) * KCH + q * 8;
                asm volatile("cp.async.ca.shared.global [%0], [%1], 16;" :: "r"(dst), "l"(src) : "memory");
            }
            asm volatile("cp.async.commit_group;" ::: "memory");
            asm volatile("cp.async.wait_group 1;" ::: "memory");   // chunk c's B done
        } else {
            asm volatile("cp.async.wait_group 0;" ::: "memory");
        }
        __syncthreads();

        // ---- MMA over buf: 4 ksteps, 8 ldsm : 32 MMAs each ----
        #pragma unroll
        for (int ks = 0; ks < 4; ks++) {
            uint32_t af[4][4];
            #pragma unroll
            for (int mf = 0; mf < 4; mf++)
                ldsm4(af[mf], sA + (uint32_t)((wm * 64 + mf * 16 + aRowL) * LDA + ks * 16 + aKoff) * 2);
            uint32_t bf[8][2];
            #pragma unroll
            for (int q = 0; q < 4; q++) {
                uint32_t r[4];
                ldsm4(r, sB + (uint32_t)((wn * 64 + q * 16 + bNoff) * LDB + ks * 16 + bKoff) * 2);
                bf[2 * q][0] = r[0]; bf[2 * q][1] = r[1];
                bf[2 * q + 1][0] = r[2]; bf[2 * q + 1][1] = r[3];
            }
            #pragma unroll
            for (int mf = 0; mf < 4; mf++)
                #pragma unroll
                for (int o = 0; o < 8; o++)
                    mma16816(d[mf][o], af[mf], bf[o]);
        }
        __syncthreads();
    }

    // ---- epilogue ----
    const int colBase = blk * BSZ + wn * 64 + (lane & 3) * 2;
    const int rowBase = mTile * 128 + wm * 64 + (lane >> 2);
    #pragma unroll
    for (int mf = 0; mf < 4; mf++) {
        float* r0 = out + (size_t)(rowBase + mf * 16) * LAYER + colBase;
        float* r1 = r0 + 8 * LAYER;
        #pragma unroll
        for (int o = 0; o < 8; o++) {
            *reinterpret_cast<float2*>(r0 + o * 8) = make_float2(d[mf][o][0], d[mf][o][1]);
            *reinterpret_cast<float2*>(r1 + o * 8) = make_float2(d[mf][o][2], d[mf][o][3]);
        }
    }
}

// ---------------- launch ----------------
extern "C" void kernel_launch(void* const* d_in, const int* in_sizes, int n_in,
                              void* d_out, int out_size) {
    const float* x      = (const float*)d_in[0];
    const float* blocks = (const float*)d_in[1];
    float* out = (float*)d_out;
    (void)in_sizes; (void)n_in; (void)out_size;

    cudaFuncSetAttribute(bd_mma, cudaFuncAttributeMaxDynamicSharedMemorySize, SM_TOTAL);

    prep_B<<<dim3(8, NBLK), 256>>>(blocks);
    bd_mma<<<dim3(NROWS / 128, NBLK), 256, SM_TOTAL>>>(x, out);
}